// round 11
// baseline (speedup 1.0000x reference)
#include <cuda_runtime.h>
#include <cstdint>

// Top-4 mean pooling: (512, 2048, 7, 7) fp32 -> 1,048,576 rows of 49 floats,
// out[row] = mean(top4(row)).
//
// R11 = R8 (best: cp.async 4-stage ring, 2 threads/row, bitonic pair-merge)
// with the block split in half: 128 threads over 64-row tiles -> 4 blocks/SM
// (4 x 50,176 B smem). Same warps/SM (16) and same in-flight DRAM demand as
// R8, but 4 independent sync domains per SM instead of 2: one block's
// barrier/wait serial phase overlaps the other three blocks' compute/fill,
// and each barrier gates 4 warps instead of 8.
//
// Compute per thread (proven R8): even thread scans global idx [0,24] of its
// row, odd scans [24,48] with overlap slot 0 masked to -inf; each keeps a
// sorted top-4 (sort4 + 7-op FMNMX insert chain); pair-merged via shfl.xor(1)
// + bitonic split (max-half of A ++ reverse(P) = union's top-4 multiset).

#define ROW_LEN 49
#define TROWS 64
#define NTHREADS 128
#define TILE_FLOATS (TROWS * ROW_LEN)              // 3136
#define STAGES 4
#define SMEM_BYTES (STAGES * TILE_FLOATS * 4)      // 50,176
#define NBLOCKS 592                                // 148 SMs * 4 blocks

__device__ __forceinline__ void cpa16(float* smem_dst, const float4* gsrc) {
    uint32_t s = (uint32_t)__cvta_generic_to_shared(smem_dst);
    asm volatile("cp.async.cg.shared.global [%0], [%1], 16;" :: "r"(s), "l"(gsrc));
}

__device__ __forceinline__ void issue_tile_load(const float* __restrict__ in,
                                                float* dst, int t, int ntiles,
                                                int tid) {
    if (t < ntiles) {
        const float4* src = reinterpret_cast<const float4*>(in + (size_t)t * TILE_FLOATS);
        #pragma unroll
        for (int i = tid; i < TILE_FLOATS / 4; i += NTHREADS)
            cpa16(dst + 4 * i, src + i);
    }
    asm volatile("cp.async.commit_group;");   // commit even if empty: keep group count aligned
}

__global__ __launch_bounds__(NTHREADS)
void apool_topk4_pair64(const float* __restrict__ in,
                        float* __restrict__ out,
                        int ntiles) {
    extern __shared__ float buf[];            // [STAGES][TILE_FLOATS]
    const int tid = threadIdx.x;
    const int stride = gridDim.x;
    const int myrow = tid >> 1;               // 0..63
    const int odd = tid & 1;
    const float NEG_INF = __int_as_float(0xff800000);

    int t = blockIdx.x;
    // Prologue: fill ALL 4 stages with tiles t .. t+3*stride.
    #pragma unroll
    for (int s = 0; s < STAGES; s++)
        issue_tile_load(in, buf + s * TILE_FLOATS, t + s * stride, ntiles, tid);

    int stage = 0;
    for (; t < ntiles; t += stride) {
        asm volatile("cp.async.wait_group 3;");   // oldest of 4 groups retired
        __syncthreads();                          // block-wide visibility

        const int row = t * TROWS + myrow;
        // even: idx 0..24 (base +0); odd: idx 24..48 (base +24), slot 0 masked.
        const float* r = &buf[stage * TILE_FLOATS + myrow * ROW_LEN + odd * 24];

        // Sort first 4 of the half descending; odd masks slot 0 (overlap).
        float a = odd ? NEG_INF : r[0];
        float b = r[1], c = r[2], d = r[3];
        float tt;
        #define CE(x, y) { tt = fmaxf(x, y); y = fminf(x, y); x = tt; }
        CE(a, b); CE(c, d); CE(a, c); CE(b, d); CE(b, c);
        #undef CE

        // Insert slots 4..24 (7-op carry-down chain each).
        #pragma unroll
        for (int i = 4; i < 25; i++) {
            float v = r[i];
            float na = fmaxf(a, v); v = fminf(a, v); a = na;
            float nb = fmaxf(b, v); v = fminf(b, v); b = nb;
            float nc = fmaxf(c, v); v = fminf(c, v); c = nc;
            d = fmaxf(d, v);
        }

        // Pair merge via bitonic split: partner's sorted-4 reversed, take maxes.
        float pa = __shfl_xor_sync(0xffffffffu, a, 1);
        float pb = __shfl_xor_sync(0xffffffffu, b, 1);
        float pc = __shfl_xor_sync(0xffffffffu, c, 1);
        float pd = __shfl_xor_sync(0xffffffffu, d, 1);
        float res = (fmaxf(a, pd) + fmaxf(b, pc) + fmaxf(c, pb) + fmaxf(d, pa)) * 0.25f;

        __syncthreads();                          // everyone done reading this stage
        // Refill CURRENT stage with tile t+4*stride (next tenant of this slot).
        issue_tile_load(in, buf + stage * TILE_FLOATS, t + STAGES * stride,
                        ntiles, tid);

        if (!odd) out[row] = res;                 // even lanes: consecutive rows

        stage = (stage + 1) & (STAGES - 1);
    }
}

// Tail rows (nrows % TROWS != 0) — not hit for this shape; trivial direct path.
__global__ void apool_topk4_tail(const float* __restrict__ in,
                                 float* __restrict__ out,
                                 int row0, int nrows) {
    const int row = row0 + blockIdx.x * blockDim.x + threadIdx.x;
    if (row >= nrows) return;
    const float* r = in + (size_t)row * ROW_LEN;
    float a = r[0], b = r[1], c = r[2], d = r[3];
    float tt;
    #define CE(x, y) { tt = fmaxf(x, y); y = fminf(x, y); x = tt; }
    CE(a, b); CE(c, d); CE(a, c); CE(b, d); CE(b, c);
    #undef CE
    for (int i = 4; i < ROW_LEN; i++) {
        float v = r[i];
        float na = fmaxf(a, v); v = fminf(a, v); a = na;
        float nb = fmaxf(b, v); v = fminf(b, v); b = nb;
        float nc = fmaxf(c, v); v = fminf(c, v); c = nc;
        d = fmaxf(d, v);
    }
    out[row] = (a + b + c + d) * 0.25f;
}

extern "C" void kernel_launch(void* const* d_in, const int* in_sizes, int n_in,
                              void* d_out, int out_size) {
    const float* in = (const float*)d_in[0];
    float* out = (float*)d_out;
    const int nrows = in_sizes[0] / ROW_LEN;     // 1,048,576
    const int ntiles = nrows / TROWS;            // 16,384 full tiles
    const int rem = nrows - ntiles * TROWS;      // 0 for this shape

    static bool attr_set = false;
    if (!attr_set) {
        cudaFuncSetAttribute(apool_topk4_pair64,
                             cudaFuncAttributeMaxDynamicSharedMemorySize,
                             SMEM_BYTES);
        attr_set = true;
    }
    const int grid = (ntiles < NBLOCKS) ? ntiles : NBLOCKS;
    if (ntiles > 0)
        apool_topk4_pair64<<<grid, NTHREADS, SMEM_BYTES>>>(in, out, ntiles);
    if (rem > 0)
        apool_topk4_tail<<<(rem + 127) / 128, 128>>>(in, out,
                                                     ntiles * TROWS, nrows);
}

// round 12
// speedup vs baseline: 1.0106x; 1.0106x over previous
#include <cuda_runtime.h>
#include <cstdint>

// Top-4 mean pooling: (512, 2048, 7, 7) fp32 -> 1,048,576 rows of 49 floats,
// out[row] = mean(top4(row)).
//
// R12 = R8 (cp.async 4-stage ring, 256 thr / 128-row tiles, 2 threads/row,
// bitonic pair-merge) + EARLY STAGE RELEASE: each thread first copies its 25
// smem slots into registers, then the block barriers and issues the refill
// for this stage, and only THEN runs the FMNMX top-4 chain from registers.
// Previously the refill sat behind the full ~900-cyc compute phase (LDS reads
// interleaved with compute kept the stage live), serializing DRAM delivery
// with compute -> the 71%-DRAM plateau seen in R8/R10/R11. Now the stage is
// freed ~200 cyc after the wait and the refill's DRAM time overlaps compute.
//
// Compute per thread (proven): even thread covers row idx [0,24], odd covers
// [24,48] with overlap slot 0 masked to -inf; sorted top-4 via sort4 + 7-op
// insert chain; pair merge via shfl.xor(1) + bitonic split.

#define ROW_LEN 49
#define TROWS 128
#define NTHREADS 256
#define TILE_FLOATS (TROWS * ROW_LEN)              // 6272
#define STAGES 4
#define SMEM_BYTES (STAGES * TILE_FLOATS * 4)      // 100,352
#define NBLOCKS 296                                // 148 SMs * 2 blocks

__device__ __forceinline__ void cpa16(float* smem_dst, const float4* gsrc) {
    uint32_t s = (uint32_t)__cvta_generic_to_shared(smem_dst);
    asm volatile("cp.async.cg.shared.global [%0], [%1], 16;" :: "r"(s), "l"(gsrc));
}

__device__ __forceinline__ void issue_tile_load(const float* __restrict__ in,
                                                float* dst, int t, int ntiles,
                                                int tid) {
    if (t < ntiles) {
        const float4* src = reinterpret_cast<const float4*>(in + (size_t)t * TILE_FLOATS);
        #pragma unroll
        for (int i = tid; i < TILE_FLOATS / 4; i += NTHREADS)
            cpa16(dst + 4 * i, src + i);
    }
    asm volatile("cp.async.commit_group;");   // commit even if empty: keep group count aligned
}

__global__ __launch_bounds__(NTHREADS)
void apool_topk4_early(const float* __restrict__ in,
                       float* __restrict__ out,
                       int ntiles) {
    extern __shared__ float buf[];            // [STAGES][TILE_FLOATS]
    const int tid = threadIdx.x;
    const int stride = gridDim.x;
    const int myrow = tid >> 1;               // 0..127
    const int odd = tid & 1;
    const float NEG_INF = __int_as_float(0xff800000);

    int t = blockIdx.x;
    // Prologue: fill ALL 4 stages with tiles t .. t+3*stride.
    #pragma unroll
    for (int s = 0; s < STAGES; s++)
        issue_tile_load(in, buf + s * TILE_FLOATS, t + s * stride, ntiles, tid);

    int stage = 0;
    for (; t < ntiles; t += stride) {
        asm volatile("cp.async.wait_group 3;");   // oldest of 4 groups retired
        __syncthreads();                          // block-wide visibility

        // ---- Phase 1: drain this thread's 25 slots into registers ----
        const float* r = &buf[stage * TILE_FLOATS + myrow * ROW_LEN + odd * 24];
        float v[25];
        #pragma unroll
        for (int i = 0; i < 25; i++) v[i] = r[i];

        __syncthreads();                          // ALL reads done -> stage free
        // ---- Phase 2: refill this stage EARLY (overlaps compute below) ----
        issue_tile_load(in, buf + stage * TILE_FLOATS, t + STAGES * stride,
                        ntiles, tid);

        // ---- Phase 3: compute from registers ----
        // Sort first 4 descending; odd masks slot 0 (the overlap element).
        float a = odd ? NEG_INF : v[0];
        float b = v[1], c = v[2], d = v[3];
        float tt;
        #define CE(x, y) { tt = fmaxf(x, y); y = fminf(x, y); x = tt; }
        CE(a, b); CE(c, d); CE(a, c); CE(b, d); CE(b, c);
        #undef CE

        #pragma unroll
        for (int i = 4; i < 25; i++) {
            float w = v[i];
            float na = fmaxf(a, w); w = fminf(a, w); a = na;
            float nb = fmaxf(b, w); w = fminf(b, w); b = nb;
            float nc = fmaxf(c, w); w = fminf(c, w); c = nc;
            d = fmaxf(d, w);
        }

        // Pair merge via bitonic split.
        float pa = __shfl_xor_sync(0xffffffffu, a, 1);
        float pb = __shfl_xor_sync(0xffffffffu, b, 1);
        float pc = __shfl_xor_sync(0xffffffffu, c, 1);
        float pd = __shfl_xor_sync(0xffffffffu, d, 1);
        float res = (fmaxf(a, pd) + fmaxf(b, pc) + fmaxf(c, pb) + fmaxf(d, pa)) * 0.25f;

        if (!odd) out[t * TROWS + myrow] = res;   // even lanes: consecutive rows

        stage = (stage + 1) & (STAGES - 1);
    }
}

// Tail rows (nrows % TROWS != 0) — not hit for this shape; trivial direct path.
__global__ void apool_topk4_tail(const float* __restrict__ in,
                                 float* __restrict__ out,
                                 int row0, int nrows) {
    const int row = row0 + blockIdx.x * blockDim.x + threadIdx.x;
    if (row >= nrows) return;
    const float* r = in + (size_t)row * ROW_LEN;
    float a = r[0], b = r[1], c = r[2], d = r[3];
    float tt;
    #define CE(x, y) { tt = fmaxf(x, y); y = fminf(x, y); x = tt; }
    CE(a, b); CE(c, d); CE(a, c); CE(b, d); CE(b, c);
    #undef CE
    for (int i = 4; i < ROW_LEN; i++) {
        float v = r[i];
        float na = fmaxf(a, v); v = fminf(a, v); a = na;
        float nb = fmaxf(b, v); v = fminf(b, v); b = nb;
        float nc = fmaxf(c, v); v = fminf(c, v); c = nc;
        d = fmaxf(d, v);
    }
    out[row] = (a + b + c + d) * 0.25f;
}

extern "C" void kernel_launch(void* const* d_in, const int* in_sizes, int n_in,
                              void* d_out, int out_size) {
    const float* in = (const float*)d_in[0];
    float* out = (float*)d_out;
    const int nrows = in_sizes[0] / ROW_LEN;     // 1,048,576
    const int ntiles = nrows / TROWS;            // 8192 full tiles
    const int rem = nrows - ntiles * TROWS;      // 0 for this shape

    static bool attr_set = false;
    if (!attr_set) {
        cudaFuncSetAttribute(apool_topk4_early,
                             cudaFuncAttributeMaxDynamicSharedMemorySize,
                             SMEM_BYTES);
        attr_set = true;
    }
    const int grid = (ntiles < NBLOCKS) ? ntiles : NBLOCKS;
    if (ntiles > 0)
        apool_topk4_early<<<grid, NTHREADS, SMEM_BYTES>>>(in, out, ntiles);
    if (rem > 0)
        apool_topk4_tail<<<(rem + 127) / 128, 128>>>(in, out,
                                                     ntiles * TROWS, nrows);
}